// round 7
// baseline (speedup 1.0000x reference)
#include <cuda_runtime.h>
#include <math.h>
#include <stdint.h>

#define NDIM     128
#define TABK     512
#define BMAXF    8.0f
#define INV_BMAX 0.125f
#define ATT_SCALE 0.08838834764831845f  // 1/sqrt(128)
#define MAX_GRAPHS 16384
#define CAP      1024                    // smem attn cache per graph (nodes)
#define CHUNK    16                      // nodes per bulk copy (16*512B = 8KB)

// -------- persistent device scratch (static allocation only) --------
__device__ float g_M[2][NDIM];               // Wq @ Wk^T
__device__ float g_Kb[2];                    // Wk @ bq
__device__ int   g_start[MAX_GRAPHS];        // per-graph node offsets
__device__ float g_psi[2][TABK + 1][NDIM];   // charge_embed table psi_j(beta)

__device__ __forceinline__ float silu_f(float z) {
    return z / (1.0f + expf(-z));
}
__device__ __forceinline__ float softplus_fast(float s) {
    return fmaxf(s, 0.0f) + __logf(1.0f + __expf(-fabsf(s)));
}

__device__ __forceinline__ uint32_t smem_u32(const void* p) {
    uint32_t a;
    asm("{ .reg .u64 t; cvta.to.shared.u64 t, %1; cvt.u32.u64 %0, t; }"
        : "=r"(a) : "l"(p));
    return a;
}
#define MBAR_INIT(mb, cnt) \
    asm volatile("mbarrier.init.shared.b64 [%0], %1;" :: "r"(mb), "r"(cnt) : "memory")
#define MBAR_EXPECT_TX(mb, bytes) \
    asm volatile("mbarrier.arrive.expect_tx.shared.b64 _, [%0], %1;" \
                 :: "r"(mb), "r"(bytes) : "memory")
#define BULK_G2S(dst, src, bytes, mb) \
    asm volatile("cp.async.bulk.shared::cta.global.mbarrier::complete_tx::bytes " \
                 "[%0], [%1], %2, [%3];" \
                 :: "r"(dst), "l"(src), "r"(bytes), "r"(mb) : "memory")
#define MBAR_WAIT(mb, parity) do {                                             \
    asm volatile(                                                              \
        "{\n\t.reg .pred P;\n\t"                                               \
        "W%=:\n\t"                                                             \
        "mbarrier.try_wait.parity.acquire.cta.shared::cta.b64 P, [%0], %1, 0x989680;\n\t" \
        "@P bra.uni D%=;\n\t"                                                  \
        "bra.uni W%=;\n\t"                                                     \
        "D%=:\n\t}"                                                            \
        :: "r"(mb), "r"(parity) : "memory");                                   \
} while (0)

// ================= aux kernel: table | starts | prep (unchanged R6) =========
#define TPB_T 16
#define NTB   ((TABK + 1 + TPB_T - 1) / TPB_T)   // 33
#define SB    40

__global__ __launch_bounds__(256) void aux_kernel(
    const void* __restrict__ batch_raw, int ngraphs, int nnodes,
    const float* __restrict__ Wq, const float* __restrict__ bq,
    const float* __restrict__ Wk, const float* __restrict__ Wv,
    const float* __restrict__ W1, const float* __restrict__ b1,
    const float* __restrict__ W2, const float* __restrict__ b2) {
    int bid = blockIdx.x;
    int tid = threadIdx.x;

    if (bid < 2 * NTB) {
        if (tid >= 128) return;
        int j  = bid / NTB;
        int tb = bid - j * NTB;
        int n  = tid;
        float u2 = 0.f;
        #pragma unroll 8
        for (int ee = 0; ee < NDIM; ee++)
            u2 = fmaf(Wv[j * NDIM + ee], W1[ee * NDIM + n], u2);
        __shared__ float h1s[TPB_T][NDIM];
        float b1n = b1[n];
        #pragma unroll
        for (int tt = 0; tt < TPB_T; tt++) {
            int t = tb * TPB_T + tt;
            if (t > TABK) break;
            float x = (float)t / (float)TABK;
            float beta = BMAXF * x * x;
            h1s[tt][n] = silu_f(fmaf(beta, u2, b1n));
        }
        __syncthreads();
        float b2n = b2[n];
        float wv = Wv[j * NDIM + n];
        for (int tt = 0; tt < TPB_T; tt++) {
            int t = tb * TPB_T + tt;
            if (t > TABK) break;
            float y = 0.f;
            #pragma unroll 8
            for (int d = 0; d < NDIM; d++) y = fmaf(h1s[tt][d], W2[d * NDIM + n], y);
            float x = (float)t / (float)TABK;
            float beta = BMAXF * x * x;
            g_psi[j][t][n] = fmaf(beta, wv, silu_f(y + b2n));
        }
    } else if (bid < 2 * NTB + SB) {
        int g = (bid - 2 * NTB) * 256 + tid;
        if (g > ngraphs) return;
        const int* b32 = (const int*)batch_raw;
        int w = (nnodes >= 8) ? ((nnodes & ~1) - 6) : 0;
        bool is64 = (b32[w + 1] == 0) && (b32[w + 3] == 0) && (b32[w + 5] == 0);
        const long long* b64 = (const long long*)batch_raw;
        long long gv = (long long)g;
        int lo = 0, hi = nnodes;
        while (lo < hi) {
            int mid = (lo + hi) >> 1;
            long long val = is64 ? b64[mid] : (long long)b32[mid];
            if (val < gv) lo = mid + 1; else hi = mid;
        }
        g_start[g] = lo;
    } else {
        int j = tid >> 7, e = tid & 127;
        const float* wk = Wk + j * NDIM;
        float m = 0.f;
        #pragma unroll 8
        for (int d = 0; d < NDIM; d++) m = fmaf(Wq[e * NDIM + d], wk[d], m);
        g_M[j][e] = m;
        if (tid < 2) {
            float kb = 0.f;
            for (int d = 0; d < NDIM; d++) kb = fmaf(Wk[tid * NDIM + d], bq[d], kb);
            g_Kb[tid] = kb;
        }
    }
}

// ===== main: bulk-async double-buffered pipeline, 1 graph / 128-thr block ====
__global__ __launch_bounds__(128) void main_kernel(
    const float* __restrict__ ns, const float* __restrict__ charge,
    float* __restrict__ out, int ngraphs) {
    cudaGridDependencySynchronize();     // PDL wait on aux, before any access

    __shared__ __align__(128) float buf[2][CHUNK * NDIM];   // 2 x 8KB
    __shared__ float sm_attn[CAP];
    __shared__ float warpsum[4];
    __shared__ __align__(8) unsigned long long mbar_s[2];

    int tid  = threadIdx.x;
    int wid  = tid >> 5, lane = tid & 31;
    int l8   = tid & 7;                 // lane within 8-lane group
    int gid  = tid >> 3;                // group 0..15 (one node per group per chunk)

    uint32_t mb0 = smem_u32(&mbar_s[0]);
    uint32_t mb1 = smem_u32(&mbar_s[1]);
    if (tid == 0) { MBAR_INIT(mb0, 1); MBAR_INIT(mb1, 1); }
    __syncthreads();

    int g = blockIdx.x;
    if (g >= ngraphs) return;

    float q  = charge[g];
    float r0 = fmaxf(q, 0.f), r1 = fmaxf(-q, 0.f);
    float c0 = fminf(r0, 1.f), c1 = fminf(r1, 1.f);
    float cg = c0 * g_Kb[0] + c1 * g_Kb[1];
    int   jj = (q < 0.f) ? 1 : 0;
    float qb = fmaxf(r0, r1);
    int n0 = g_start[g], n1 = g_start[g + 1];
    int gsize = n1 - n0;
    if (gsize <= 0) return;
    int nchunks = (gsize + CHUNK - 1) / CHUNK;

    // combined projection Mc = c0*M0 + c1*M1, this lane's 16-float slice
    float4 Mc[4];
    #pragma unroll
    for (int jc = 0; jc < 4; jc++) {
        int e = jc * 32 + l8 * 4;
        float4 a = *reinterpret_cast<const float4*>(&g_M[0][e]);
        float4 b = *reinterpret_cast<const float4*>(&g_M[1][e]);
        Mc[jc].x = c0 * a.x + c1 * b.x;
        Mc[jc].y = c0 * a.y + c1 * b.y;
        Mc[jc].z = c0 * a.z + c1 * b.z;
        Mc[jc].w = c0 * a.w + c1 * b.w;
    }

    uint32_t mb[2] = { mb0, mb1 };
    uint32_t dst[2] = { smem_u32(&buf[0][0]), smem_u32(&buf[1][0]) };
    int ph[2] = { 0, 0 };

    // ================= PHASE A: pipelined dot + softplus sum =================
    if (tid == 0) {
        uint32_t bytes0 = (uint32_t)min(CHUNK, gsize) * (NDIM * 4);
        MBAR_EXPECT_TX(mb[0], bytes0);
        BULK_G2S(dst[0], (const void*)(ns + (long)n0 * NDIM), bytes0, mb[0]);
    }
    float acc = 0.f;
    for (int i = 0; i < nchunks; i++) {
        int b = i & 1;
        int base = n0 + i * CHUNK;
        if (tid == 0 && i + 1 < nchunks) {
            int nb = 1 - b;
            uint32_t bytes = (uint32_t)min(CHUNK, n1 - (base + CHUNK)) * (NDIM * 4);
            MBAR_EXPECT_TX(mb[nb], bytes);
            BULK_G2S(dst[nb], (const void*)(ns + (long)(base + CHUNK) * NDIM),
                     bytes, mb[nb]);
        }
        MBAR_WAIT(mb[b], ph[b]); ph[b] ^= 1;

        int node = base + gid;
        float s = 0.f;
        if (node < n1) {
            const float* r = &buf[b][gid * NDIM + l8 * 4];
            #pragma unroll
            for (int jc = 0; jc < 4; jc++) {
                float4 v = *reinterpret_cast<const float4*>(r + jc * 32);
                s += v.x * Mc[jc].x + v.y * Mc[jc].y + v.z * Mc[jc].z + v.w * Mc[jc].w;
            }
        }
        s += __shfl_xor_sync(0xffffffffu, s, 1);
        s += __shfl_xor_sync(0xffffffffu, s, 2);
        s += __shfl_xor_sync(0xffffffffu, s, 4);
        if (node < n1 && l8 == 0) {
            float attn = softplus_fast((s + cg) * ATT_SCALE);
            acc += attn;
            int li = node - n0;
            if (li < CAP) sm_attn[li] = attn;
        }
        __syncthreads();   // all consumed buf[b]; safe to reissue into it
    }
    #pragma unroll
    for (int o = 16; o > 0; o >>= 1) acc += __shfl_xor_sync(0xffffffffu, acc, o);
    if (lane == 0) warpsum[wid] = acc;
    __syncthreads();
    float inv = 1.0f / (warpsum[0] + warpsum[1] + warpsum[2] + warpsum[3]);

    // ================= PHASE B: pipelined table epilogue =================
    if (tid == 0) {
        uint32_t bytes0 = (uint32_t)min(CHUNK, gsize) * (NDIM * 4);
        MBAR_EXPECT_TX(mb[0], bytes0);
        BULK_G2S(dst[0], (const void*)(ns + (long)n0 * NDIM), bytes0, mb[0]);
    }
    for (int i = 0; i < nchunks; i++) {
        int b = i & 1;
        int base = n0 + i * CHUNK;
        if (tid == 0 && i + 1 < nchunks) {
            int nb = 1 - b;
            uint32_t bytes = (uint32_t)min(CHUNK, n1 - (base + CHUNK)) * (NDIM * 4);
            MBAR_EXPECT_TX(mb[nb], bytes);
            BULK_G2S(dst[nb], (const void*)(ns + (long)(base + CHUNK) * NDIM),
                     bytes, mb[nb]);
        }
        MBAR_WAIT(mb[b], ph[b]); ph[b] ^= 1;

        int node = base + gid;
        bool valid = node < n1;
        float attn = 0.f;
        if (gsize <= CAP) {                      // uniform branch over block
            if (valid) attn = sm_attn[node - n0];
        } else {                                 // uniform fallback: recompute
            float s = 0.f;
            if (valid) {
                const float* r = &buf[b][gid * NDIM + l8 * 4];
                #pragma unroll
                for (int jc = 0; jc < 4; jc++) {
                    float4 v = *reinterpret_cast<const float4*>(r + jc * 32);
                    s += v.x * Mc[jc].x + v.y * Mc[jc].y + v.z * Mc[jc].z + v.w * Mc[jc].w;
                }
            }
            s += __shfl_xor_sync(0xffffffffu, s, 1);
            s += __shfl_xor_sync(0xffffffffu, s, 2);
            s += __shfl_xor_sync(0xffffffffu, s, 4);
            attn = softplus_fast((s + cg) * ATT_SCALE);
        }
        if (valid) {
            float beta = attn * inv * qb;
            float tf = (float)TABK * sqrtf(beta * INV_BMAX);
            int idx = (int)tf;
            if (idx > TABK - 1) idx = TABK - 1;
            float f = tf - (float)idx;
            const float* pa = &g_psi[jj][idx][0];
            const float* r = &buf[b][gid * NDIM];
            float* orow = out + (long)node * NDIM;
            #pragma unroll
            for (int jc = 0; jc < 4; jc++) {
                int e = jc * 32 + l8 * 4;
                float4 v = *reinterpret_cast<const float4*>(r + e);
                float4 a = *reinterpret_cast<const float4*>(pa + e);
                float4 bb = *reinterpret_cast<const float4*>(pa + NDIM + e);
                float4 o4;
                o4.x = v.x + fmaf(f, bb.x - a.x, a.x);
                o4.y = v.y + fmaf(f, bb.y - a.y, a.y);
                o4.z = v.z + fmaf(f, bb.z - a.z, a.z);
                o4.w = v.w + fmaf(f, bb.w - a.w, a.w);
                __stcs(reinterpret_cast<float4*>(orow + e), o4);
            }
        }
        __syncthreads();
    }
}

extern "C" void kernel_launch(void* const* d_in, const int* in_sizes, int n_in,
                              void* d_out, int out_size) {
    const float* ns     = (const float*)d_in[0];
    const float* charge = (const float*)d_in[1];
    const void*  batch  = (const void*) d_in[2];
    const float* Wq     = (const float*)d_in[3];
    const float* bq     = (const float*)d_in[4];
    const float* Wk     = (const float*)d_in[5];
    const float* Wv     = (const float*)d_in[6];
    const float* W1     = (const float*)d_in[7];
    const float* b1     = (const float*)d_in[8];
    const float* W2     = (const float*)d_in[9];
    const float* b2     = (const float*)d_in[10];
    float* out = (float*)d_out;

    int nnodes  = in_sizes[0] / NDIM;
    int ngraphs = in_sizes[1];

    aux_kernel<<<2 * NTB + SB + 1, 256>>>(batch, ngraphs, nnodes,
                                          Wq, bq, Wk, Wv, W1, b1, W2, b2);

    cudaLaunchConfig_t cfg = {};
    cfg.gridDim  = dim3((unsigned)ngraphs, 1, 1);
    cfg.blockDim = dim3(128, 1, 1);
    cfg.dynamicSmemBytes = 0;
    cfg.stream = 0;
    cudaLaunchAttribute attrs[1];
    attrs[0].id = cudaLaunchAttributeProgrammaticStreamSerialization;
    attrs[0].val.programmaticStreamSerializationAllowed = 1;
    cfg.attrs = attrs;
    cfg.numAttrs = 1;
    cudaLaunchKernelEx(&cfg, main_kernel, ns, charge, out, ngraphs);
}